// round 4
// baseline (speedup 1.0000x reference)
#include <cuda_runtime.h>
#include <cuda_bf16.h>
#include <math.h>

// Problem constants
#define S 1024
#define D 2048
#define H 32
#define G 2
#define HPG 16          // heads per group
#define DQ 128
#define DV 128
#define BLOCK 64
#define C 16            // S / BLOCK
#define TOPN 4
#define WINDOW 256
#define SNEG -1e30f

// ---------------- device scratch (no allocations allowed) ----------------
__device__ float g_q[S * H * DQ];        // 16 MB  (S, H, DQ) post-RoPE
__device__ float g_k[S * G * DQ];        // 1 MB   (S, G, DQ) post-RoPE
__device__ float g_v[S * G * DV];        // 1 MB
__device__ float g_gates[S * H * 3];     // 0.4 MB (sigmoid applied)
__device__ float g_kc[C * G * DQ];       // block-mean K
__device__ float g_vc[C * G * DV];       // block-mean V
__device__ float g_o[S * H * DV];        // 16 MB  gated attention output

// ---------------- generic tiled fp32 GEMM: C = A(MxK) @ B(KxN) ----------------
// ACT: 0 = none, 1 = sigmoid
template <int ACT>
__global__ void __launch_bounds__(256) gemm_kernel(const float* __restrict__ A,
                                                   const float* __restrict__ B,
                                                   float* __restrict__ Co,
                                                   int M, int N, int K) {
    __shared__ float As[32][65];  // [k][m], padded against bank conflicts
    __shared__ float Bs[32][64];  // [k][n]
    const int bm0 = blockIdx.y * 64;
    const int bn0 = blockIdx.x * 64;
    const int tid = threadIdx.x;
    const int tm = (tid >> 4) << 2;   // 0..60
    const int tn = (tid & 15) << 2;   // 0..60

    float acc[4][4] = {};

    for (int k0 = 0; k0 < K; k0 += 32) {
        // load A tile 64x32 (M,K always multiples of tile here)
        #pragma unroll
        for (int i = tid; i < 64 * 32; i += 256) {
            int r = i >> 5, c = i & 31;
            As[c][r] = A[(bm0 + r) * K + k0 + c];
        }
        // load B tile 32x64 with N guard
        #pragma unroll
        for (int i = tid; i < 32 * 64; i += 256) {
            int r = i >> 6, c = i & 63;
            int col = bn0 + c;
            Bs[r][c] = (col < N) ? B[(k0 + r) * N + col] : 0.f;
        }
        __syncthreads();
        #pragma unroll
        for (int kk = 0; kk < 32; kk++) {
            float a0 = As[kk][tm + 0], a1 = As[kk][tm + 1];
            float a2 = As[kk][tm + 2], a3 = As[kk][tm + 3];
            float b0 = Bs[kk][tn + 0], b1 = Bs[kk][tn + 1];
            float b2 = Bs[kk][tn + 2], b3 = Bs[kk][tn + 3];
            acc[0][0] += a0 * b0; acc[0][1] += a0 * b1; acc[0][2] += a0 * b2; acc[0][3] += a0 * b3;
            acc[1][0] += a1 * b0; acc[1][1] += a1 * b1; acc[1][2] += a1 * b2; acc[1][3] += a1 * b3;
            acc[2][0] += a2 * b0; acc[2][1] += a2 * b1; acc[2][2] += a2 * b2; acc[2][3] += a2 * b3;
            acc[3][0] += a3 * b0; acc[3][1] += a3 * b1; acc[3][2] += a3 * b2; acc[3][3] += a3 * b3;
        }
        __syncthreads();
    }
    #pragma unroll
    for (int i = 0; i < 4; i++) {
        #pragma unroll
        for (int j = 0; j < 4; j++) {
            int col = bn0 + tn + j;
            if (col < N) {
                float v = acc[i][j];
                if (ACT == 1) v = 1.f / (1.f + expf(-v));
                Co[(bm0 + tm + i) * N + col] = v;
            }
        }
    }
}

// ---------------- RoPE in-place on q and k ----------------
// grid: (S, H+G); block: 64 threads
__global__ void rope_kernel(const float* __restrict__ cosp, const float* __restrict__ sinp) {
    int s = blockIdx.x;
    int hb = blockIdx.y;
    int d = threadIdx.x;  // 0..63
    float* ptr;
    if (hb < H) ptr = g_q + (s * H + hb) * DQ;
    else        ptr = g_k + (s * G + (hb - H)) * DQ;
    float c1 = cosp[s * DQ + d],      s1 = sinp[s * DQ + d];
    float c2 = cosp[s * DQ + d + 64], s2 = sinp[s * DQ + d + 64];
    float a = ptr[d];
    float b = ptr[d + 64];
    ptr[d]      = a * c1 - b * s1;   // rot[d] = -t[d+64]
    ptr[d + 64] = b * c2 + a * s2;   // rot[d+64] = t[d]
}

// ---------------- block means ----------------
// grid: (C, G); block: 128
__global__ void mean_kernel() {
    int c = blockIdx.x, g = blockIdx.y, d = threadIdx.x;
    float sk = 0.f, sv = 0.f;
    for (int j = 0; j < BLOCK; j++) {
        sk += g_k[((c * BLOCK + j) * G + g) * DQ + d];
        sv += g_v[((c * BLOCK + j) * G + g) * DV + d];
    }
    g_kc[(c * G + g) * DQ + d] = sk * (1.f / 64.f);
    g_vc[(c * G + g) * DV + d] = sv * (1.f / 64.f);
}

// ---------------- fused NSA attention per (s, g) ----------------
// compressed attn + importance + exact top-k + selected attn + window attn + gates
// grid: (S, G); block: 256 threads
__global__ void __launch_bounds__(256) attn_kernel() {
    const int s = blockIdx.x;
    const int g = blockIdx.y;
    const int tid = threadIdx.x;
    const float scale = 0.08838834764831845f;  // 1/sqrt(128)

    __shared__ float sq[HPG][DQ];        // 8 KB   q for 16 heads
    __shared__ float sc[HPG][260];       // 16.6KB scores (256 used, padded)
    __shared__ float acc[HPG][DV];       // 8 KB   gated output accumulator
    __shared__ float tile[16][132];      // 8.25KB K/V tile (16 keys, padded)
    __shared__ float pcs[HPG][16];       // compressed probs
    __shared__ float imp[16];
    __shared__ float sg[HPG][3];
    __shared__ int   sidx[TOPN];

    // load q (post-RoPE), gates; zero accumulator
    for (int i = tid; i < HPG * DQ; i += 256) {
        int h = i >> 7, d = i & 127;
        sq[h][d]  = g_q[(s * H + g * HPG + h) * DQ + d];
        acc[h][d] = 0.f;
    }
    if (tid < HPG * 3) {
        int h = tid / 3, cc = tid % 3;
        sg[h][cc] = g_gates[s * H * 3 + (g * HPG + h) * 3 + cc];
    }
    __syncthreads();

    // ======== compressed branch ========
    const int nfull = (s + 1) >> 6;  // number of fully formed blocks
    {
        int h = tid >> 4, c = tid & 15;
        const float4* qp  = (const float4*)sq[h];
        const float4* kcp = (const float4*)(g_kc + (c * G + g) * DQ);
        float dot = 0.f;
        #pragma unroll
        for (int d4 = 0; d4 < 32; d4++) {
            float4 a = qp[d4], b = kcp[d4];
            dot += a.x * b.x + a.y * b.y + a.z * b.z + a.w * b.w;
        }
        pcs[h][c] = dot * scale;
    }
    __syncthreads();
    if (tid < HPG) {
        int h = tid;
        if (nfull == 0) {
            for (int c = 0; c < 16; c++) pcs[h][c] = 0.f;
        } else {
            float m = -1e38f;
            for (int c = 0; c < nfull; c++) m = fmaxf(m, pcs[h][c]);
            float ssum = 0.f;
            for (int c = 0; c < nfull; c++) { float e = expf(pcs[h][c] - m); pcs[h][c] = e; ssum += e; }
            float inv = 1.f / ssum;
            for (int c = 0; c < 16; c++) pcs[h][c] = (c < nfull) ? pcs[h][c] * inv : 0.f;
        }
    }
    __syncthreads();
    if (tid < 16) {
        int c = tid; float sum = 0.f;
        for (int h = 0; h < HPG; h++) sum += pcs[h][c];
        imp[c] = sum;
    }
    // o_cmp accumulation (gate 0)
    for (int i = tid; i < HPG * DV; i += 256) {
        int h = i >> 7, d = i & 127;
        float v = 0.f;
        for (int c = 0; c < nfull; c++) v += pcs[h][c] * g_vc[(c * G + g) * DV + d];
        acc[h][d] += sg[h][0] * v;
    }
    __syncthreads();

    // ======== top-k selection (exact jax.lax.top_k tie-break: lowest index wins) ========
    if (tid == 0) {
        int cur = s >> 6;
        float iv[16];
        for (int c = 0; c < 16; c++) {
            bool valid = (c * BLOCK) <= s;
            bool force = (c == 0) || (c == cur);
            iv[c] = (valid && force) ? 1e9f : (valid ? imp[c] : -1e9f);
        }
        bool used[16] = {};
        for (int n = 0; n < TOPN; n++) {
            float best = -1e38f; int bi = 0;
            for (int c = 0; c < 16; c++)
                if (!used[c] && iv[c] > best) { best = iv[c]; bi = c; }
            used[bi] = true;
            sidx[n] = bi;
        }
    }
    __syncthreads();

    // ======== selected-blocks branch (TOPN*BLOCK = 256 keys) ========
    for (int T = 0; T < 16; T++) {
        for (int i = tid; i < 16 * DQ; i += 256) {
            int tt = i >> 7, d = i & 127;
            int kk = T * 16 + tt;
            int t = sidx[kk >> 6] * BLOCK + (kk & 63);
            tile[tt][d] = g_k[(t * G + g) * DQ + d];
        }
        __syncthreads();
        {
            int h = tid >> 4, tt = tid & 15;
            int kk = T * 16 + tt;
            int t = sidx[kk >> 6] * BLOCK + (kk & 63);
            const float4* qp = (const float4*)sq[h];
            const float4* kp = (const float4*)tile[tt];
            float dot = 0.f;
            #pragma unroll
            for (int d4 = 0; d4 < 32; d4++) {
                float4 a = qp[d4], b = kp[d4];
                dot += a.x * b.x + a.y * b.y + a.z * b.z + a.w * b.w;
            }
            sc[h][kk] = (t <= s) ? dot * scale : SNEG;
        }
        __syncthreads();
    }
    if (tid < HPG) {
        int h = tid;
        float m = -1e38f;
        for (int kk = 0; kk < 256; kk++) m = fmaxf(m, sc[h][kk]);
        float ssum = 0.f;
        for (int kk = 0; kk < 256; kk++) { float e = expf(sc[h][kk] - m); sc[h][kk] = e; ssum += e; }
        float inv = 1.f / ssum;
        for (int kk = 0; kk < 256; kk++) sc[h][kk] *= inv;
    }
    __syncthreads();
    {
        float accr[8];
        #pragma unroll
        for (int r = 0; r < 8; r++) accr[r] = 0.f;
        for (int T = 0; T < 16; T++) {
            for (int i = tid; i < 16 * DV; i += 256) {
                int tt = i >> 7, d = i & 127;
                int kk = T * 16 + tt;
                int t = sidx[kk >> 6] * BLOCK + (kk & 63);
                tile[tt][d] = g_v[(t * G + g) * DV + d];
            }
            __syncthreads();
            #pragma unroll
            for (int r = 0; r < 8; r++) {
                int o = tid + 256 * r;
                int h = o >> 7, d = o & 127;
                float vs = 0.f;
                #pragma unroll
                for (int tt = 0; tt < 16; tt++) vs += sc[h][T * 16 + tt] * tile[tt][d];
                accr[r] += vs;
            }
            __syncthreads();
        }
        #pragma unroll
        for (int r = 0; r < 8; r++) {
            int o = tid + 256 * r;
            int h = o >> 7, d = o & 127;
            acc[h][d] += sg[h][1] * accr[r];
        }
    }
    __syncthreads();

    // ======== sliding-window branch (keys t = s-255 .. s) ========
    for (int T = 0; T < 16; T++) {
        for (int i = tid; i < 16 * DQ; i += 256) {
            int tt = i >> 7, d = i & 127;
            int t = s - 255 + T * 16 + tt;
            tile[tt][d] = (t >= 0) ? g_k[(t * G + g) * DQ + d] : 0.f;
        }
        __syncthreads();
        {
            int h = tid >> 4, tt = tid & 15;
            int kk = T * 16 + tt;
            int t = s - 255 + kk;
            const float4* qp = (const float4*)sq[h];
            const float4* kp = (const float4*)tile[tt];
            float dot = 0.f;
            #pragma unroll
            for (int d4 = 0; d4 < 32; d4++) {
                float4 a = qp[d4], b = kp[d4];
                dot += a.x * b.x + a.y * b.y + a.z * b.z + a.w * b.w;
            }
            sc[h][kk] = (t >= 0) ? dot * scale : SNEG;
        }
        __syncthreads();
    }
    if (tid < HPG) {
        int h = tid;
        float m = -1e38f;
        for (int kk = 0; kk < 256; kk++) m = fmaxf(m, sc[h][kk]);
        float ssum = 0.f;
        for (int kk = 0; kk < 256; kk++) { float e = expf(sc[h][kk] - m); sc[h][kk] = e; ssum += e; }
        float inv = 1.f / ssum;
        for (int kk = 0; kk < 256; kk++) sc[h][kk] *= inv;
    }
    __syncthreads();
    {
        float accr[8];
        #pragma unroll
        for (int r = 0; r < 8; r++) accr[r] = 0.f;
        for (int T = 0; T < 16; T++) {
            for (int i = tid; i < 16 * DV; i += 256) {
                int tt = i >> 7, d = i & 127;
                int t = s - 255 + T * 16 + tt;
                tile[tt][d] = (t >= 0) ? g_v[(t * G + g) * DV + d] : 0.f;
            }
            __syncthreads();
            #pragma unroll
            for (int r = 0; r < 8; r++) {
                int o = tid + 256 * r;
                int h = o >> 7, d = o & 127;
                float vs = 0.f;
                #pragma unroll
                for (int tt = 0; tt < 16; tt++) vs += sc[h][T * 16 + tt] * tile[tt][d];
                accr[r] += vs;
            }
            __syncthreads();
        }
        #pragma unroll
        for (int r = 0; r < 8; r++) {
            int o = tid + 256 * r;
            int h = o >> 7, d = o & 127;
            acc[h][d] += sg[h][2] * accr[r];
        }
    }
    __syncthreads();

    // write gated output
    for (int i = tid; i < HPG * DV; i += 256) {
        int h = i >> 7, d = i & 127;
        g_o[(s * H + g * HPG + h) * DV + d] = acc[h][d];
    }
}

// ---------------- host launch ----------------
static float* sym_addr(const void* sym) {
    void* p = nullptr;
    cudaGetSymbolAddress(&p, sym);
    return (float*)p;
}

extern "C" void kernel_launch(void* const* d_in, const int* in_sizes, int n_in,
                              void* d_out, int out_size) {
    const float* x    = (const float*)d_in[0];
    const float* cosp = (const float*)d_in[1];
    const float* sinp = (const float*)d_in[2];
    const float* Wq   = (const float*)d_in[3];
    const float* Wk   = (const float*)d_in[4];
    const float* Wv   = (const float*)d_in[5];
    const float* Wo   = (const float*)d_in[6];
    const float* Wc   = (const float*)d_in[7];
    float* out = (float*)d_out;

    float* q  = sym_addr(g_q);
    float* k  = sym_addr(g_k);
    float* v  = sym_addr(g_v);
    float* gt = sym_addr(g_gates);
    float* o  = sym_addr(g_o);

    // projections
    gemm_kernel<0><<<dim3((H * DQ) / 64, S / 64), 256>>>(x, Wq, q, S, H * DQ, D);
    gemm_kernel<0><<<dim3((G * DQ) / 64, S / 64), 256>>>(x, Wk, k, S, G * DQ, D);
    gemm_kernel<0><<<dim3((G * DV) / 64, S / 64), 256>>>(x, Wv, v, S, G * DV, D);
    gemm_kernel<1><<<dim3((H * 3 + 63) / 64, S / 64), 256>>>(x, Wc, gt, S, H * 3, D);

    // RoPE on q and k
    rope_kernel<<<dim3(S, H + G), 64>>>(cosp, sinp);

    // block means
    mean_kernel<<<dim3(C, G), 128>>>();

    // fused NSA attention
    attn_kernel<<<dim3(S, G), 256>>>();

    // output projection
    gemm_kernel<0><<<dim3(D / 64, S / 64), 256>>>(o, Wo, out, S, D, H * DV);
}

// round 14
// speedup vs baseline: 1.0909x; 1.0909x over previous
#include <cuda_runtime.h>
#include <cuda_bf16.h>
#include <math.h>
#include <stdint.h>

// Problem constants
#define S 1024
#define D 2048
#define H 32
#define G 2
#define HPG 16          // heads per group
#define DQ 128
#define DV 128
#define BLOCK 64
#define C 16            // S / BLOCK
#define TOPN 4
#define WINDOW 256
#define SNEG -1e30f

// ---------------- device scratch (no allocations allowed) ----------------
__device__ float g_q[S * H * DQ];        // (S, H, DQ) post-RoPE
__device__ float g_k[S * G * DQ];
__device__ float g_v[S * G * DV];
__device__ float g_gates[S * H * 3];     // sigmoid applied
__device__ float g_kc[C * G * DQ];
__device__ float g_vc[C * G * DV];
__device__ float g_o[S * H * DV];

// ---------------- 3xTF32 tensor-core GEMM: C = A(MxK) @ B(KxN) ----------------
// Each fp32 operand is split a = hi + lo (hi = tf32(a), lo = tf32(a - hi)).
// acc += hi*hi + lo*hi + hi*lo  -> near-fp32 accuracy on tensor cores.
__device__ __forceinline__ uint32_t f2tf32(float x) {
    uint32_t r;
    asm("cvt.rna.tf32.f32 %0, %1;" : "=r"(r) : "f"(x));
    return r;
}

__device__ __forceinline__ void split_tf32(float v, uint32_t& hi, uint32_t& lo) {
    hi = f2tf32(v);
    lo = f2tf32(v - __uint_as_float(hi));
}

__device__ __forceinline__ void mma_tf32(float c[4],
                                         uint32_t a0, uint32_t a1, uint32_t a2, uint32_t a3,
                                         uint32_t b0, uint32_t b1) {
    asm volatile(
        "mma.sync.aligned.m16n8k8.row.col.f32.tf32.tf32.f32 "
        "{%0,%1,%2,%3}, {%4,%5,%6,%7}, {%8,%9}, {%0,%1,%2,%3};\n"
        : "+f"(c[0]), "+f"(c[1]), "+f"(c[2]), "+f"(c[3])
        : "r"(a0), "r"(a1), "r"(a2), "r"(a3), "r"(b0), "r"(b1));
}

// Tile: BM x BN x 32. 256 threads = 8 warps in 2x4.
// ACT: 0 = none, 1 = sigmoid
template <int ACT, int BM, int BN>
__global__ void __launch_bounds__(256) gemm_tc(const float* __restrict__ A,
                                               const float* __restrict__ B,
                                               float* __restrict__ Co,
                                               int M, int N, int K) {
    constexpr int MT = BM / 32;          // m16 tiles per warp
    constexpr int NT = BN / 32;          // n8 tiles per warp
    constexpr int WTM = BM / 2;
    constexpr int WTN = BN / 4;
    constexpr int BSTRIDE = BN + 8;      // (BN+8) % 32 == 8 -> conflict-free frags

    __shared__ float As[BM][36];         // m-major fp32, stride 36 (c.f.)
    __shared__ float Bs[32][BSTRIDE];    // k-major fp32

    const int tid  = threadIdx.x;
    const int warp = tid >> 5, lane = tid & 31;
    const int wr = warp >> 2, wc = warp & 3;  // 2 x 4 warp grid
    const int gid = lane >> 2, tig = lane & 3;
    const int bm0 = blockIdx.y * BM;
    const int bn0 = blockIdx.x * BN;

    float acc[MT][NT][4];
    #pragma unroll
    for (int i = 0; i < MT; i++)
        #pragma unroll
        for (int j = 0; j < NT; j++)
            #pragma unroll
            for (int r = 0; r < 4; r++) acc[i][j][r] = 0.f;

    for (int k0 = 0; k0 < K; k0 += 32) {
        // ---- load A tile BMx32 (row-major gmem, m-major smem), float4 along k
        #pragma unroll
        for (int i = tid; i < BM * 8; i += 256) {
            int r = i >> 3, c = (i & 7) << 2;
            float4 v = *(const float4*)&A[(size_t)(bm0 + r) * K + k0 + c];
            *(float4*)&As[r][c] = v;
        }
        // ---- load B tile 32xBN (k-major), float4 along n with N guard
        #pragma unroll
        for (int i = tid; i < 32 * (BN / 4); i += 256) {
            int r = i / (BN / 4), c = (i % (BN / 4)) << 2;
            int col = bn0 + c;
            float4 v;
            if (col + 3 < N) {
                v = *(const float4*)&B[(size_t)(k0 + r) * N + col];
            } else {
                v.x = (col + 0 < N) ? B[(size_t)(k0 + r) * N + col + 0] : 0.f;
                v.y = (col + 1 < N) ? B[(size_t)(k0 + r) * N + col + 1] : 0.f;
                v.z = (col + 2 < N) ? B[(size_t)(k0 + r) * N + col + 2] : 0.f;
                v.w = (col + 3 < N) ? B[(size_t)(k0 + r) * N + col + 3] : 0.f;
            }
            *(float4*)&Bs[r][c] = v;
        }
        __syncthreads();

        #pragma unroll
        for (int ks = 0; ks < 4; ks++) {
            const int k8 = ks * 8;
            uint32_t ah[MT][4], al[MT][4], bh[NT][2], bl[NT][2];
            #pragma unroll
            for (int mt = 0; mt < MT; mt++) {
                int row = wr * WTM + mt * 16 + gid;
                split_tf32(As[row][k8 + tig],         ah[mt][0], al[mt][0]);
                split_tf32(As[row + 8][k8 + tig],     ah[mt][1], al[mt][1]);
                split_tf32(As[row][k8 + tig + 4],     ah[mt][2], al[mt][2]);
                split_tf32(As[row + 8][k8 + tig + 4], ah[mt][3], al[mt][3]);
            }
            #pragma unroll
            for (int nt = 0; nt < NT; nt++) {
                int col = wc * WTN + nt * 8 + gid;
                split_tf32(Bs[k8 + tig][col],     bh[nt][0], bl[nt][0]);
                split_tf32(Bs[k8 + tig + 4][col], bh[nt][1], bl[nt][1]);
            }
            #pragma unroll
            for (int mt = 0; mt < MT; mt++)
                #pragma unroll
                for (int nt = 0; nt < NT; nt++) {
                    // lo terms first, hi*hi last (slightly better summation order)
                    mma_tf32(acc[mt][nt], al[mt][0], al[mt][1], al[mt][2], al[mt][3],
                             bh[nt][0], bh[nt][1]);
                    mma_tf32(acc[mt][nt], ah[mt][0], ah[mt][1], ah[mt][2], ah[mt][3],
                             bl[nt][0], bl[nt][1]);
                    mma_tf32(acc[mt][nt], ah[mt][0], ah[mt][1], ah[mt][2], ah[mt][3],
                             bh[nt][0], bh[nt][1]);
                }
        }
        __syncthreads();
    }

    // ---- epilogue: c0->(r,c) c1->(r,c+1) c2->(r+8,c) c3->(r+8,c+1)
    #pragma unroll
    for (int mt = 0; mt < MT; mt++) {
        #pragma unroll
        for (int nt = 0; nt < NT; nt++) {
            int row = bm0 + wr * WTM + mt * 16 + gid;
            int col = bn0 + wc * WTN + nt * 8 + tig * 2;
            float v0 = acc[mt][nt][0], v1 = acc[mt][nt][1];
            float v2 = acc[mt][nt][2], v3 = acc[mt][nt][3];
            if (ACT == 1) {
                v0 = 1.f / (1.f + expf(-v0));
                v1 = 1.f / (1.f + expf(-v1));
                v2 = 1.f / (1.f + expf(-v2));
                v3 = 1.f / (1.f + expf(-v3));
            }
            if (col + 1 < N) {
                *(float2*)&Co[(size_t)row * N + col]       = make_float2(v0, v1);
                *(float2*)&Co[(size_t)(row + 8) * N + col] = make_float2(v2, v3);
            } else if (col < N) {
                Co[(size_t)row * N + col]       = v0;
                Co[(size_t)(row + 8) * N + col] = v2;
            }
        }
    }
}

// ---------------- RoPE in-place on q and k ----------------
__global__ void rope_kernel(const float* __restrict__ cosp, const float* __restrict__ sinp) {
    int s = blockIdx.x;
    int hb = blockIdx.y;
    int d = threadIdx.x;  // 0..63
    float* ptr;
    if (hb < H) ptr = g_q + (s * H + hb) * DQ;
    else        ptr = g_k + (s * G + (hb - H)) * DQ;
    float c1 = cosp[s * DQ + d],      s1 = sinp[s * DQ + d];
    float c2 = cosp[s * DQ + d + 64], s2 = sinp[s * DQ + d + 64];
    float a = ptr[d];
    float b = ptr[d + 64];
    ptr[d]      = a * c1 - b * s1;
    ptr[d + 64] = b * c2 + a * s2;
}

// ---------------- block means ----------------
__global__ void mean_kernel() {
    int c = blockIdx.x, g = blockIdx.y, d = threadIdx.x;
    float sk = 0.f, sv = 0.f;
    for (int j = 0; j < BLOCK; j++) {
        sk += g_k[((c * BLOCK + j) * G + g) * DQ + d];
        sv += g_v[((c * BLOCK + j) * G + g) * DV + d];
    }
    g_kc[(c * G + g) * DQ + d] = sk * (1.f / 64.f);
    g_vc[(c * G + g) * DV + d] = sv * (1.f / 64.f);
}

// ---------------- parallel 256-wide softmax: 16 lanes per head ----------------
__device__ __forceinline__ void softmax256(float sc[HPG][260], int tid) {
    int h = tid >> 4, l = tid & 15;
    float m = -1e38f;
    #pragma unroll
    for (int kk = 0; kk < 256; kk += 16) m = fmaxf(m, sc[h][kk + l]);
    #pragma unroll
    for (int o = 8; o; o >>= 1) m = fmaxf(m, __shfl_xor_sync(0xffffffffu, m, o));
    float ssum = 0.f;
    #pragma unroll
    for (int kk = 0; kk < 256; kk += 16) {
        float e = expf(sc[h][kk + l] - m);
        sc[h][kk + l] = e;
        ssum += e;
    }
    #pragma unroll
    for (int o = 8; o; o >>= 1) ssum += __shfl_xor_sync(0xffffffffu, ssum, o);
    float inv = 1.f / ssum;
    #pragma unroll
    for (int kk = 0; kk < 256; kk += 16) sc[h][kk + l] *= inv;
}

// ---------------- fused NSA attention per (s, g) ----------------
__global__ void __launch_bounds__(256) attn_kernel() {
    const int s = blockIdx.x;
    const int g = blockIdx.y;
    const int tid = threadIdx.x;
    const float scale = 0.08838834764831845f;  // 1/sqrt(128)

    __shared__ float sq[HPG][DQ];
    __shared__ float sc[HPG][260];
    __shared__ float acc[HPG][DV];
    __shared__ float tile[16][132];
    __shared__ float pcs[HPG][16];
    __shared__ float imp[16];
    __shared__ float sg[HPG][3];
    __shared__ int   sidx[TOPN];

    for (int i = tid; i < HPG * DQ; i += 256) {
        int h = i >> 7, d = i & 127;
        sq[h][d]  = g_q[(s * H + g * HPG + h) * DQ + d];
        acc[h][d] = 0.f;
    }
    if (tid < HPG * 3) {
        int h = tid / 3, cc = tid % 3;
        sg[h][cc] = g_gates[s * H * 3 + (g * HPG + h) * 3 + cc];
    }
    __syncthreads();

    // ======== compressed branch ========
    const int nfull = (s + 1) >> 6;
    {
        int h = tid >> 4, c = tid & 15;
        const float4* qp  = (const float4*)sq[h];
        const float4* kcp = (const float4*)(g_kc + (c * G + g) * DQ);
        float dot = 0.f;
        #pragma unroll
        for (int d4 = 0; d4 < 32; d4++) {
            float4 a = qp[d4], b = kcp[d4];
            dot += a.x * b.x + a.y * b.y + a.z * b.z + a.w * b.w;
        }
        pcs[h][c] = dot * scale;
    }
    __syncthreads();
    if (tid < HPG) {
        int h = tid;
        if (nfull == 0) {
            for (int c = 0; c < 16; c++) pcs[h][c] = 0.f;
        } else {
            float m = -1e38f;
            for (int c = 0; c < nfull; c++) m = fmaxf(m, pcs[h][c]);
            float ssum = 0.f;
            for (int c = 0; c < nfull; c++) { float e = expf(pcs[h][c] - m); pcs[h][c] = e; ssum += e; }
            float inv = 1.f / ssum;
            for (int c = 0; c < 16; c++) pcs[h][c] = (c < nfull) ? pcs[h][c] * inv : 0.f;
        }
    }
    __syncthreads();
    if (tid < 16) {
        int c = tid; float sum = 0.f;
        for (int h = 0; h < HPG; h++) sum += pcs[h][c];
        imp[c] = sum;
    }
    for (int i = tid; i < HPG * DV; i += 256) {
        int h = i >> 7, d = i & 127;
        float v = 0.f;
        for (int c = 0; c < nfull; c++) v += pcs[h][c] * g_vc[(c * G + g) * DV + d];
        acc[h][d] += sg[h][0] * v;
    }
    __syncthreads();

    // ======== top-k selection (exact jax.lax.top_k tie-break) ========
    if (tid == 0) {
        int cur = s >> 6;
        float iv[16];
        for (int c = 0; c < 16; c++) {
            bool valid = (c * BLOCK) <= s;
            bool force = (c == 0) || (c == cur);
            iv[c] = (valid && force) ? 1e9f : (valid ? imp[c] : -1e9f);
        }
        bool used[16] = {};
        for (int n = 0; n < TOPN; n++) {
            float best = -1e38f; int bi = 0;
            for (int c = 0; c < 16; c++)
                if (!used[c] && iv[c] > best) { best = iv[c]; bi = c; }
            used[bi] = true;
            sidx[n] = bi;
        }
    }
    __syncthreads();

    // ======== selected-blocks branch ========
    for (int T = 0; T < 16; T++) {
        for (int i = tid; i < 16 * DQ; i += 256) {
            int tt = i >> 7, d = i & 127;
            int kk = T * 16 + tt;
            int t = sidx[kk >> 6] * BLOCK + (kk & 63);
            tile[tt][d] = g_k[(t * G + g) * DQ + d];
        }
        __syncthreads();
        {
            int h = tid >> 4, tt = tid & 15;
            int kk = T * 16 + tt;
            int t = sidx[kk >> 6] * BLOCK + (kk & 63);
            const float4* qp = (const float4*)sq[h];
            const float4* kp = (const float4*)tile[tt];
            float dot = 0.f;
            #pragma unroll
            for (int d4 = 0; d4 < 32; d4++) {
                float4 a = qp[d4], b = kp[d4];
                dot += a.x * b.x + a.y * b.y + a.z * b.z + a.w * b.w;
            }
            sc[h][kk] = (t <= s) ? dot * scale : SNEG;
        }
        __syncthreads();
    }
    softmax256(sc, tid);
    __syncthreads();
    {
        float accr[8];
        #pragma unroll
        for (int r = 0; r < 8; r++) accr[r] = 0.f;
        for (int T = 0; T < 16; T++) {
            for (int i = tid; i < 16 * DV; i += 256) {
                int tt = i >> 7, d = i & 127;
                int kk = T * 16 + tt;
                int t = sidx[kk >> 6] * BLOCK + (kk & 63);
                tile[tt][d] = g_v[(t * G + g) * DV + d];
            }
            __syncthreads();
            #pragma unroll
            for (int r = 0; r < 8; r++) {
                int o = tid + 256 * r;
                int h = o >> 7, d = o & 127;
                float vs = 0.f;
                #pragma unroll
                for (int tt = 0; tt < 16; tt++) vs += sc[h][T * 16 + tt] * tile[tt][d];
                accr[r] += vs;
            }
            __syncthreads();
        }
        #pragma unroll
        for (int r = 0; r < 8; r++) {
            int o = tid + 256 * r;
            int h = o >> 7, d = o & 127;
            acc[h][d] += sg[h][1] * accr[r];
        }
    }
    __syncthreads();

    // ======== sliding-window branch ========
    for (int T = 0; T < 16; T++) {
        for (int i = tid; i < 16 * DQ; i += 256) {
            int tt = i >> 7, d = i & 127;
            int t = s - 255 + T * 16 + tt;
            tile[tt][d] = (t >= 0) ? g_k[(t * G + g) * DQ + d] : 0.f;
        }
        __syncthreads();
        {
            int h = tid >> 4, tt = tid & 15;
            int kk = T * 16 + tt;
            int t = s - 255 + kk;
            const float4* qp = (const float4*)sq[h];
            const float4* kp = (const float4*)tile[tt];
            float dot = 0.f;
            #pragma unroll
            for (int d4 = 0; d4 < 32; d4++) {
                float4 a = qp[d4], b = kp[d4];
                dot += a.x * b.x + a.y * b.y + a.z * b.z + a.w * b.w;
            }
            sc[h][kk] = (t >= 0) ? dot * scale : SNEG;
        }
        __syncthreads();
    }
    softmax256(sc, tid);
    __syncthreads();
    {
        float accr[8];
        #pragma unroll
        for (int r = 0; r < 8; r++) accr[r] = 0.f;
        for (int T = 0; T < 16; T++) {
            for (int i = tid; i < 16 * DV; i += 256) {
                int tt = i >> 7, d = i & 127;
                int t = s - 255 + T * 16 + tt;
                tile[tt][d] = (t >= 0) ? g_v[(t * G + g) * DV + d] : 0.f;
            }
            __syncthreads();
            #pragma unroll
            for (int r = 0; r < 8; r++) {
                int o = tid + 256 * r;
                int h = o >> 7, d = o & 127;
                float vs = 0.f;
                #pragma unroll
                for (int tt = 0; tt < 16; tt++) vs += sc[h][T * 16 + tt] * tile[tt][d];
                accr[r] += vs;
            }
            __syncthreads();
        }
        #pragma unroll
        for (int r = 0; r < 8; r++) {
            int o = tid + 256 * r;
            int h = o >> 7, d = o & 127;
            acc[h][d] += sg[h][2] * accr[r];
        }
    }
    __syncthreads();

    for (int i = tid; i < HPG * DV; i += 256) {
        int h = i >> 7, d = i & 127;
        g_o[(s * H + g * HPG + h) * DV + d] = acc[h][d];
    }
}

// ---------------- host launch ----------------
static float* sym_addr(const void* sym) {
    void* p = nullptr;
    cudaGetSymbolAddress(&p, sym);
    return (float*)p;
}

extern "C" void kernel_launch(void* const* d_in, const int* in_sizes, int n_in,
                              void* d_out, int out_size) {
    const float* x    = (const float*)d_in[0];
    const float* cosp = (const float*)d_in[1];
    const float* sinp = (const float*)d_in[2];
    const float* Wq   = (const float*)d_in[3];
    const float* Wk   = (const float*)d_in[4];
    const float* Wv   = (const float*)d_in[5];
    const float* Wo   = (const float*)d_in[6];
    const float* Wc   = (const float*)d_in[7];
    float* out = (float*)d_out;

    float* q  = sym_addr(g_q);
    float* k  = sym_addr(g_k);
    float* v  = sym_addr(g_v);
    float* gt = sym_addr(g_gates);
    float* o  = sym_addr(g_o);

    // projections (3xTF32 tensor cores)
    gemm_tc<0,128,128><<<dim3((H * DQ) / 128, S / 128), 256>>>(x, Wq, q, S, H * DQ, D);
    gemm_tc<0, 64, 64><<<dim3((G * DQ) / 64,  S / 64),  256>>>(x, Wk, k, S, G * DQ, D);
    gemm_tc<0, 64, 64><<<dim3((G * DV) / 64,  S / 64),  256>>>(x, Wv, v, S, G * DV, D);
    gemm_tc<1, 64, 64><<<dim3((H * 3 + 63) / 64, S / 64), 256>>>(x, Wc, gt, S, H * 3, D);

    // RoPE on q and k
    rope_kernel<<<dim3(S, H + G), 64>>>(cosp, sinp);

    // block means
    mean_kernel<<<dim3(C, G), 128>>>();

    // fused NSA attention
    attn_kernel<<<dim3(S, G), 256>>>();

    // output projection (3xTF32 tensor cores)
    gemm_tc<0,128,128><<<dim3(D / 128, S / 128), 256>>>(o, Wo, out, S, D, H * DV);
}